// round 10
// baseline (speedup 1.0000x reference)
#include <cuda_runtime.h>
#include <cuda_bf16.h>

#define THREADS 256
#define SPT 8

typedef unsigned long long u64;

struct Quat { float w, x, y, z; };

__device__ __forceinline__ u64 pk2(float lo, float hi) {
    u64 r; asm("mov.b64 %0, {%1, %2};" : "=l"(r) : "f"(lo), "f"(hi)); return r;
}
__device__ __forceinline__ void up2(u64 v, float& lo, float& hi) {
    asm("mov.b64 {%0, %1}, %2;" : "=f"(lo), "=f"(hi) : "l"(v));
}
__device__ __forceinline__ u64 fma2(u64 a, u64 b, u64 c) {
    u64 r; asm("fma.rn.f32x2 %0, %1, %2, %3;" : "=l"(r) : "l"(a), "l"(b), "l"(c)); return r;
}
__device__ __forceinline__ u64 mul2(u64 a, u64 b) {
    u64 r; asm("mul.rn.f32x2 %0, %1, %2;" : "=l"(r) : "l"(a), "l"(b)); return r;
}
__device__ __forceinline__ u64 add2(u64 a, u64 b) {
    u64 r; asm("add.rn.f32x2 %0, %1, %2;" : "=l"(r) : "l"(a), "l"(b)); return r;
}
__device__ __forceinline__ u64 abs2(u64 v) { return v & 0x7FFFFFFF7FFFFFFFULL; }

// general quaternion product (tree combines)
__device__ __forceinline__ Quat qmul(const Quat a, const Quat b) {
    Quat o;
    o.w = a.w * b.w - a.x * b.x - a.y * b.y - a.z * b.z;
    o.x = a.w * b.x + a.x * b.w + a.y * b.z - a.z * b.y;
    o.y = a.w * b.y - a.x * b.z + a.y * b.w + a.z * b.x;
    o.z = a.w * b.z + a.x * b.y - a.y * b.x + a.z * b.w;
    return o;
}

// a * (1, dx, dy, dz) — 12 FFMA
__device__ __forceinline__ Quat qmul_unit(const Quat a, float dx, float dy, float dz) {
    Quat o;
    o.w = fmaf(-a.x, dx, fmaf(-a.y, dy, fmaf(-a.z, dz, a.w)));
    o.x = fmaf( a.w, dx, fmaf( a.y, dz, fmaf(-a.z, dy, a.x)));
    o.y = fmaf( a.w, dy, fmaf(-a.x, dz, fmaf( a.z, dx, a.y)));
    o.z = fmaf( a.w, dz, fmaf( a.x, dy, fmaf(-a.y, dx, a.z)));
    return o;
}

__global__ __launch_bounds__(THREADS, 2)
void tinygc2l_kernel(const float* __restrict__ ts,
                     const float* __restrict__ gyro,
                     const float* __restrict__ q0g,
                     const float* __restrict__ W1,
                     const float* __restrict__ B1,
                     const float* __restrict__ A1,
                     const float* __restrict__ W2,
                     const float* __restrict__ B2,
                     const float* __restrict__ A2,
                     float* __restrict__ out,
                     int CNT)
{
    __shared__ float4 s_wq[THREADS / 32];

    const int b    = blockIdx.x;
    const int tid  = threadIdx.x;
    const int lane = tid & 31;
    const int wid  = tid >> 5;
    const int t0   = tid * SPT;

    // ---- front-batched vectorized loads: 9 points + 9 timestamps ----
    float gf[24];     // points 0..7
    float tf[9];
    float g8x, g8y, g8z;
    {
        const float4* gsrc = reinterpret_cast<const float4*>(
            gyro + (size_t)b * CNT * 3 + (size_t)t0 * 3);
        #pragma unroll
        for (int i = 0; i < 6; i++) {
            float4 v = gsrc[i];
            gf[4 * i + 0] = v.x; gf[4 * i + 1] = v.y;
            gf[4 * i + 2] = v.z; gf[4 * i + 3] = v.w;
        }
        const float4* tsrc = reinterpret_cast<const float4*>(
            ts + (size_t)b * CNT + t0);
        #pragma unroll
        for (int i = 0; i < 2; i++) {
            float4 v = tsrc[i];
            tf[4 * i + 0] = v.x; tf[4 * i + 1] = v.y;
            tf[4 * i + 2] = v.z; tf[4 * i + 3] = v.w;
        }
        const bool have8 = (t0 + 8 <= CNT - 1);
        const float* gp8 = gyro + (size_t)b * CNT * 3 + (size_t)(t0 + 8) * 3;
        g8x = have8 ? gp8[0] : 0.f;
        g8y = have8 ? gp8[1] : 0.f;
        g8z = have8 ? gp8[2] : 0.f;
        // neutralize the out-of-range final step: s = 0 => identity quaternion
        tf[8] = have8 ? ts[(size_t)b * CNT + t0 + 8] : tf[7];
    }

    // ---- packed broadcast weights ----
    u64 W1p[9], W2p[9], B1p[3], B2p[3];
    #pragma unroll
    for (int i = 0; i < 9; i++) {
        float w = __ldg(W1 + i); W1p[i] = pk2(w, w);
        float v = __ldg(W2 + i); W2p[i] = pk2(v, v);
    }
    #pragma unroll
    for (int i = 0; i < 3; i++) {
        float w = __ldg(B1 + i); B1p[i] = pk2(w, w);
        float v = __ldg(B2 + i); B2p[i] = pk2(v, v);
    }
    const float a1 = __ldg(A1);
    const float a2 = __ldg(A2);
    // prelu(x) = c1*x + c2*|x|
    const u64 C1a = pk2(0.5f * (1.f + a1), 0.5f * (1.f + a1));
    const u64 C2a = pk2(0.5f * (1.f - a1), 0.5f * (1.f - a1));
    const u64 C1b = pk2(0.5f * (1.f + a2), 0.5f * (1.f + a2));
    const u64 C2b = pk2(0.5f * (1.f - a2), 0.5f * (1.f - a2));

    // packed MLP over a pair of points (residual included)
    auto mlp2 = [&](u64& px, u64& py, u64& pz) {
        u64 h0 = fma2(W1p[0], px, fma2(W1p[1], py, fma2(W1p[2], pz, B1p[0])));
        u64 h1 = fma2(W1p[3], px, fma2(W1p[4], py, fma2(W1p[5], pz, B1p[1])));
        u64 h2 = fma2(W1p[6], px, fma2(W1p[7], py, fma2(W1p[8], pz, B1p[2])));
        h0 = fma2(C1a, h0, mul2(C2a, abs2(h0)));
        h1 = fma2(C1a, h1, mul2(C2a, abs2(h1)));
        h2 = fma2(C1a, h2, mul2(C2a, abs2(h2)));
        u64 g0 = fma2(W2p[0], h0, fma2(W2p[1], h1, fma2(W2p[2], h2, B2p[0])));
        u64 g1 = fma2(W2p[3], h0, fma2(W2p[4], h1, fma2(W2p[5], h2, B2p[1])));
        u64 g2 = fma2(W2p[6], h0, fma2(W2p[7], h1, fma2(W2p[8], h2, B2p[2])));
        g0 = fma2(C1b, g0, mul2(C2b, abs2(g0)));
        g1 = fma2(C1b, g1, mul2(C2b, abs2(g1)));
        g2 = fma2(C1b, g2, mul2(C2b, abs2(g2)));
        px = add2(g0, px); py = add2(g1, py); pz = add2(g2, pz);
    };

    // ---- pack 4 pairs of owned points + boundary pair, run packed MLP ----
    u64 PX[5], PY[5], PZ[5];
    #pragma unroll
    for (int j = 0; j < 4; j++) {
        PX[j] = pk2(gf[6 * j + 0], gf[6 * j + 3]);
        PY[j] = pk2(gf[6 * j + 1], gf[6 * j + 4]);
        PZ[j] = pk2(gf[6 * j + 2], gf[6 * j + 5]);
    }
    PX[4] = pk2(g8x, g8x);
    PY[4] = pk2(g8y, g8y);
    PZ[4] = pk2(g8z, g8z);
    #pragma unroll
    for (int j = 0; j < 5; j++) mlp2(PX[j], PY[j], PZ[j]);

    // ---- unpack to per-point scalars ----
    float gx[9], gy[9], gz[9];
    #pragma unroll
    for (int j = 0; j < 4; j++) {
        up2(PX[j], gx[2 * j], gx[2 * j + 1]);
        up2(PY[j], gy[2 * j], gy[2 * j + 1]);
        up2(PZ[j], gz[2 * j], gz[2 * j + 1]);
    }
    { float d; up2(PX[4], gx[8], d); up2(PY[4], gy[8], d); up2(PZ[4], gz[8], d); }

    // ---- ordered per-thread product, predicate-free (12-FMA unit steps) ----
    Quat p; p.w = 1.f; p.x = 0.f; p.y = 0.f; p.z = 0.f;
    #pragma unroll
    for (int i = 0; i < SPT; i++) {
        const float s  = 0.25f * (tf[i + 1] - tf[i]);
        const float dx = (gx[i] + gx[i + 1]) * s;
        const float dy = (gy[i] + gy[i + 1]) * s;
        const float dz = (gz[i] + gz[i + 1]) * s;
        p = qmul_unit(p, dx, dy, dz);
    }
    {
        const float n2 = p.w * p.w + p.x * p.x + p.y * p.y + p.z * p.z;
        const float inv = rsqrtf(fmaxf(n2, 1e-24f));
        p.w *= inv; p.x *= inv; p.y *= inv; p.z *= inv;
    }

    // ---- ordered warp tree reduction ----
    #pragma unroll
    for (int off = 1; off < 32; off <<= 1) {
        Quat q;
        q.w = __shfl_down_sync(0xffffffffu, p.w, off);
        q.x = __shfl_down_sync(0xffffffffu, p.x, off);
        q.y = __shfl_down_sync(0xffffffffu, p.y, off);
        q.z = __shfl_down_sync(0xffffffffu, p.z, off);
        if (lane + off < 32) p = qmul(p, q);
    }
    if (lane == 0) s_wq[wid] = make_float4(p.w, p.x, p.y, p.z);
    __syncthreads();

    // ---- warp 0: ordered reduce of 8 warp products, finalize ----
    if (wid == 0) {
        Quat r; r.w = 1.f; r.x = 0.f; r.y = 0.f; r.z = 0.f;
        if (lane < THREADS / 32) {
            float4 v = s_wq[lane];
            r.w = v.x; r.x = v.y; r.y = v.z; r.z = v.w;
        }
        #pragma unroll
        for (int off = 1; off < THREADS / 32; off <<= 1) {
            Quat q;
            q.w = __shfl_down_sync(0xffffffffu, r.w, off);
            q.x = __shfl_down_sync(0xffffffffu, r.x, off);
            q.y = __shfl_down_sync(0xffffffffu, r.y, off);
            q.z = __shfl_down_sync(0xffffffffu, r.z, off);
            if (lane + off < THREADS / 32) r = qmul(r, q);
        }
        if (lane == 0) {
            Quat q0;
            const float* qp = q0g + (size_t)b * 4;
            q0.w = qp[0]; q0.x = qp[1]; q0.y = qp[2]; q0.z = qp[3];
            Quat f = qmul(q0, r);
            const float n = sqrtf(f.w * f.w + f.x * f.x + f.y * f.y + f.z * f.z);
            const float inv = 1.0f / fmaxf(n, 1e-12f);
            float* op = out + (size_t)b * 4;
            op[0] = f.w * inv;
            op[1] = f.x * inv;
            op[2] = f.y * inv;
            op[3] = f.z * inv;
        }
    }
}

extern "C" void kernel_launch(void* const* d_in, const int* in_sizes, int n_in,
                              void* d_out, int out_size) {
    const float* ts   = (const float*)d_in[0];
    const float* gyro = (const float*)d_in[1];
    const float* q0   = (const float*)d_in[2];
    const float* W1   = (const float*)d_in[3];
    const float* b1   = (const float*)d_in[4];
    const float* a1   = (const float*)d_in[5];
    const float* W2   = (const float*)d_in[6];
    const float* b2   = (const float*)d_in[7];
    const float* a2   = (const float*)d_in[8];
    float* out = (float*)d_out;

    const int B   = in_sizes[2] / 4;   // start_quat is (B,4)
    const int CNT = in_sizes[0] / B;   // timestamps are (B,CNT)

    tinygc2l_kernel<<<B, THREADS>>>(ts, gyro, q0, W1, b1, a1, W2, b2, a2, out, CNT);
}

// round 11
// speedup vs baseline: 1.1182x; 1.1182x over previous
#include <cuda_runtime.h>
#include <cuda_bf16.h>

#define THREADS 256
#define SPT 8

struct Quat { float w, x, y, z; };

// general quaternion product (tree combines)
__device__ __forceinline__ Quat qmul(const Quat a, const Quat b) {
    Quat o;
    o.w = a.w * b.w - a.x * b.x - a.y * b.y - a.z * b.z;
    o.x = a.w * b.x + a.x * b.w + a.y * b.z - a.z * b.y;
    o.y = a.w * b.y - a.x * b.z + a.y * b.w + a.z * b.x;
    o.z = a.w * b.z + a.x * b.y - a.y * b.x + a.z * b.w;
    return o;
}

// a * (1, dx, dy, dz) — 12 FFMA
__device__ __forceinline__ Quat qmul_unit(const Quat a, float dx, float dy, float dz) {
    Quat o;
    o.w = fmaf(-a.x, dx, fmaf(-a.y, dy, fmaf(-a.z, dz, a.w)));
    o.x = fmaf( a.w, dx, fmaf( a.y, dz, fmaf(-a.z, dy, a.x)));
    o.y = fmaf( a.w, dy, fmaf(-a.x, dz, fmaf( a.z, dx, a.y)));
    o.z = fmaf( a.w, dz, fmaf( a.x, dy, fmaf(-a.y, dx, a.z)));
    return o;
}

__global__ __launch_bounds__(THREADS)
void tinygc2l_kernel(const float* __restrict__ ts,
                     const float* __restrict__ gyro,
                     const float* __restrict__ q0g,
                     const float* __restrict__ W1,
                     const float* __restrict__ B1,
                     const float* __restrict__ A1,
                     const float* __restrict__ W2,
                     const float* __restrict__ B2,
                     const float* __restrict__ A2,
                     float* __restrict__ out,
                     int CNT)
{
    __shared__ float4 s_wq[THREADS / 32];

    const int b    = blockIdx.x;
    const int tid  = threadIdx.x;
    const int lane = tid & 31;
    const int wid  = tid >> 5;
    const int t0   = tid * SPT;

    // ---- front-batched vectorized loads: 9 points + 9 timestamps ----
    float gf[27];     // points 0..8 (xyz interleaved)
    float tf[9];
    {
        const float4* gsrc = reinterpret_cast<const float4*>(
            gyro + (size_t)b * CNT * 3 + (size_t)t0 * 3);
        #pragma unroll
        for (int i = 0; i < 6; i++) {
            float4 v = gsrc[i];
            gf[4 * i + 0] = v.x; gf[4 * i + 1] = v.y;
            gf[4 * i + 2] = v.z; gf[4 * i + 3] = v.w;
        }
        const float4* tsrc = reinterpret_cast<const float4*>(
            ts + (size_t)b * CNT + t0);
        #pragma unroll
        for (int i = 0; i < 2; i++) {
            float4 v = tsrc[i];
            tf[4 * i + 0] = v.x; tf[4 * i + 1] = v.y;
            tf[4 * i + 2] = v.z; tf[4 * i + 3] = v.w;
        }
        // boundary point t0+8, front-batched with the tile loads (L1/L2 hit)
        const bool have8 = (t0 + 8 <= CNT - 1);
        const float* gp8 = gyro + (size_t)b * CNT * 3 + (size_t)(t0 + 8) * 3;
        gf[24] = have8 ? gp8[0] : 0.f;
        gf[25] = have8 ? gp8[1] : 0.f;
        gf[26] = have8 ? gp8[2] : 0.f;
        // neutralize out-of-range final step: dt = 0 -> identity rotation
        tf[8]  = have8 ? ts[(size_t)b * CNT + t0 + 8] : tf[7];
    }

    // ---- weights ----
    float w1[9], w2[9], bb1[3], bb2[3];
    #pragma unroll
    for (int i = 0; i < 9; i++) { w1[i] = __ldg(W1 + i); w2[i] = __ldg(W2 + i); }
    #pragma unroll
    for (int i = 0; i < 3; i++) { bb1[i] = __ldg(B1 + i); bb2[i] = __ldg(B2 + i); }
    const float a1 = __ldg(A1);
    const float a2 = __ldg(A2);
    // prelu(x) = c1*x + c2*|x|
    const float c1a = 0.5f * (1.f + a1), c2a = 0.5f * (1.f - a1);
    const float c1b = 0.5f * (1.f + a2), c2b = 0.5f * (1.f - a2);

    // ---- tiny-net on all 9 points (in place; prelu2 + residual fused) ----
    #pragma unroll
    for (int i = 0; i < 9; i++) {
        const float ix = gf[3 * i + 0];
        const float iy = gf[3 * i + 1];
        const float iz = gf[3 * i + 2];
        float h0 = fmaf(w1[0], ix, fmaf(w1[1], iy, fmaf(w1[2], iz, bb1[0])));
        float h1 = fmaf(w1[3], ix, fmaf(w1[4], iy, fmaf(w1[5], iz, bb1[1])));
        float h2 = fmaf(w1[6], ix, fmaf(w1[7], iy, fmaf(w1[8], iz, bb1[2])));
        h0 = fmaf(c2a, fabsf(h0), c1a * h0);
        h1 = fmaf(c2a, fabsf(h1), c1a * h1);
        h2 = fmaf(c2a, fabsf(h2), c1a * h2);
        const float g0 = fmaf(w2[0], h0, fmaf(w2[1], h1, fmaf(w2[2], h2, bb2[0])));
        const float g1 = fmaf(w2[3], h0, fmaf(w2[4], h1, fmaf(w2[5], h2, bb2[1])));
        const float g2 = fmaf(w2[6], h0, fmaf(w2[7], h1, fmaf(w2[8], h2, bb2[2])));
        // prelu2 + residual in 2 FMA per channel
        gf[3 * i + 0] = fmaf(c1b, g0, fmaf(c2b, fabsf(g0), ix));
        gf[3 * i + 1] = fmaf(c1b, g1, fmaf(c2b, fabsf(g1), iy));
        gf[3 * i + 2] = fmaf(c1b, g2, fmaf(c2b, fabsf(g2), iz));
    }

    // ---- ordered per-thread product, predicate-free (12-FMA unit steps) ----
    Quat p; p.w = 1.f; p.x = 0.f; p.y = 0.f; p.z = 0.f;
    #pragma unroll
    for (int i = 0; i < SPT; i++) {
        const float s  = 0.25f * (tf[i + 1] - tf[i]);
        const float dx = (gf[3 * i + 0] + gf[3 * i + 3]) * s;
        const float dy = (gf[3 * i + 1] + gf[3 * i + 4]) * s;
        const float dz = (gf[3 * i + 2] + gf[3 * i + 5]) * s;
        p = qmul_unit(p, dx, dy, dz);
    }
    {
        const float n2 = p.w * p.w + p.x * p.x + p.y * p.y + p.z * p.z;
        const float inv = rsqrtf(fmaxf(n2, 1e-24f));
        p.w *= inv; p.x *= inv; p.y *= inv; p.z *= inv;
    }

    // ---- ordered warp tree reduction ----
    #pragma unroll
    for (int off = 1; off < 32; off <<= 1) {
        Quat q;
        q.w = __shfl_down_sync(0xffffffffu, p.w, off);
        q.x = __shfl_down_sync(0xffffffffu, p.x, off);
        q.y = __shfl_down_sync(0xffffffffu, p.y, off);
        q.z = __shfl_down_sync(0xffffffffu, p.z, off);
        if (lane + off < 32) p = qmul(p, q);
    }
    if (lane == 0) s_wq[wid] = make_float4(p.w, p.x, p.y, p.z);
    __syncthreads();

    // ---- warp 0: ordered reduce of 8 warp products, finalize ----
    if (wid == 0) {
        Quat r; r.w = 1.f; r.x = 0.f; r.y = 0.f; r.z = 0.f;
        if (lane < THREADS / 32) {
            float4 v = s_wq[lane];
            r.w = v.x; r.x = v.y; r.y = v.z; r.z = v.w;
        }
        #pragma unroll
        for (int off = 1; off < THREADS / 32; off <<= 1) {
            Quat q;
            q.w = __shfl_down_sync(0xffffffffu, r.w, off);
            q.x = __shfl_down_sync(0xffffffffu, r.x, off);
            q.y = __shfl_down_sync(0xffffffffu, r.y, off);
            q.z = __shfl_down_sync(0xffffffffu, r.z, off);
            if (lane + off < THREADS / 32) r = qmul(r, q);
        }
        if (lane == 0) {
            Quat q0;
            const float* qp = q0g + (size_t)b * 4;
            q0.w = qp[0]; q0.x = qp[1]; q0.y = qp[2]; q0.z = qp[3];
            Quat f = qmul(q0, r);
            const float n = sqrtf(f.w * f.w + f.x * f.x + f.y * f.y + f.z * f.z);
            const float inv = 1.0f / fmaxf(n, 1e-12f);
            float* op = out + (size_t)b * 4;
            op[0] = f.w * inv;
            op[1] = f.x * inv;
            op[2] = f.y * inv;
            op[3] = f.z * inv;
        }
    }
}

extern "C" void kernel_launch(void* const* d_in, const int* in_sizes, int n_in,
                              void* d_out, int out_size) {
    const float* ts   = (const float*)d_in[0];
    const float* gyro = (const float*)d_in[1];
    const float* q0   = (const float*)d_in[2];
    const float* W1   = (const float*)d_in[3];
    const float* b1   = (const float*)d_in[4];
    const float* a1   = (const float*)d_in[5];
    const float* W2   = (const float*)d_in[6];
    const float* b2   = (const float*)d_in[7];
    const float* a2   = (const float*)d_in[8];
    float* out = (float*)d_out;

    const int B   = in_sizes[2] / 4;   // start_quat is (B,4)
    const int CNT = in_sizes[0] / B;   // timestamps are (B,CNT)

    tinygc2l_kernel<<<B, THREADS>>>(ts, gyro, q0, W1, b1, a1, W2, b2, a2, out, CNT);
}